// round 14
// baseline (speedup 1.0000x reference)
#include <cuda_runtime.h>
#include <cuda_fp16.h>
#include <cstdint>

#define BDIM 16384
#define HDIM 1024
constexpr size_t NBH = (size_t)BDIM * HDIM;
constexpr size_t NHH = (size_t)HDIM * HDIM;

// ---------------------------------------------------------------------------
// Scratch (static device arrays: allocation-free per harness rules)
// GEMM INPUT planes (g_x*, g_rw, g_w*) are stored TILED+SWIZZLED:
//   tile = 128 rows x 64 cols (16 KB), tiles ordered [row_blk][k_chunk]
// GEMM outputs (g_kh/g_vh/g_rh, final out) remain LINEAR.
// ---------------------------------------------------------------------------
__device__ __align__(16) __half g_kh[NBH];
__device__ __align__(16) __half g_vh[NBH];
__device__ __align__(16) __half g_rh[NBH];

__device__ __align__(16) __half g_xk[NBH];
__device__ __align__(16) __half g_xv[NBH];
__device__ __align__(16) __half g_xr[NBH];
__device__ __align__(16) __half g_rw[NBH];

__device__ __align__(16) __half g_wk[NHH];
__device__ __align__(16) __half g_wv[NHH];
__device__ __align__(16) __half g_wr[NHH];
__device__ __align__(16) __half g_wo[NHH];

__device__ int g_cnt[1024];   // per-(rowblk, colblk) arrival counters (self-resetting)

// ---------------------------------------------------------------------------
// PTX helpers (sm_90-baseline features only; legal on sm_103 base target)
// ---------------------------------------------------------------------------
__device__ __forceinline__ uint32_t smem_u32(const void* p) {
    uint32_t a;
    asm("{ .reg .u64 t; cvta.to.shared.u64 t, %1; cvt.u32.u64 %0, t; }" : "=r"(a) : "l"(p));
    return a;
}
__device__ __forceinline__ void mbar_init(uint32_t a, uint32_t cnt) {
    asm volatile("mbarrier.init.shared.b64 [%0], %1;" :: "r"(a), "r"(cnt) : "memory");
}
__device__ __forceinline__ void mbar_expect_tx(uint32_t a, uint32_t bytes) {
    asm volatile("mbarrier.arrive.expect_tx.shared.b64 _, [%0], %1;"
                 :: "r"(a), "r"(bytes) : "memory");
}
__device__ __forceinline__ void mbar_arrive(uint32_t a) {
    asm volatile("mbarrier.arrive.shared.b64 _, [%0];" :: "r"(a) : "memory");
}
__device__ __forceinline__ void mbar_wait(uint32_t a, uint32_t parity) {
    asm volatile(
        "{\n\t.reg .pred P;\n\t"
        "WL%=:\n\t"
        "mbarrier.try_wait.parity.acquire.cta.shared::cta.b64 P, [%0], %1, 0x989680;\n\t"
        "@P bra WD%=;\n\t"
        "bra WL%=;\n\t"
        "WD%=:\n\t}"
        :: "r"(a), "r"(parity) : "memory");
}
__device__ __forceinline__ void mbar_wait_relaxed(uint32_t a, uint32_t parity) {
    asm volatile(
        "{\n\t.reg .pred P;\n\t"
        "WL%=:\n\t"
        "mbarrier.try_wait.parity.relaxed.cta.shared::cta.b64 P, [%0], %1, 0x989680;\n\t"
        "@P bra WD%=;\n\t"
        "bra WL%=;\n\t"
        "WD%=:\n\t}"
        :: "r"(a), "r"(parity) : "memory");
}
__device__ __forceinline__ void cp_bulk(uint32_t dst, const void* src, uint32_t bytes,
                                        uint32_t mbar) {
    asm volatile(
        "cp.async.bulk.shared::cluster.global.mbarrier::complete_tx::bytes [%0], [%1], %2, [%3];"
        :: "r"(dst), "l"(src), "r"(bytes), "r"(mbar) : "memory");
}
__device__ __forceinline__ void ldsm4(uint32_t* r, uint32_t addr) {
    asm volatile("ldmatrix.sync.aligned.m8n8.x4.shared.b16 {%0,%1,%2,%3}, [%4];"
                 : "=r"(r[0]), "=r"(r[1]), "=r"(r[2]), "=r"(r[3]) : "r"(addr));
}
__device__ __forceinline__ void mma_f16(float* c, const uint32_t* a, uint32_t b0, uint32_t b1) {
    asm volatile(
        "mma.sync.aligned.m16n8k16.row.col.f32.f16.f16.f32 "
        "{%0,%1,%2,%3}, {%4,%5,%6,%7}, {%8,%9}, {%0,%1,%2,%3};"
        : "+f"(c[0]), "+f"(c[1]), "+f"(c[2]), "+f"(c[3])
        : "r"(a[0]), "r"(a[1]), "r"(a[2]), "r"(a[3]), "r"(b0), "r"(b1));
}

// ---------------------------------------------------------------------------
// GEMM config: CTA 128x128x64, 8 warps (4m x 2n -> warp tile 32x64), 3 stages
// ---------------------------------------------------------------------------
constexpr int BM = 128, BN = 128, BK = 64;
constexpr int NCH = HDIM / BK;              // 16
constexpr int NSTG = 3;
constexpr int PLANE_B = BM * BK * 2;        // 16384 bytes (one tile)
constexpr int STAGE_B = 2 * PLANE_B;        // 32768: [A][B]
constexpr int SMEM_STAGES_OFF = 1024;       // barriers + flag live below
constexpr int SMEM_TOT = SMEM_STAGES_OFF + NSTG * STAGE_B;  // 99328

// within-tile swizzled offset (bytes): row 0..127, 16B chunk 0..7
__device__ __forceinline__ uint32_t swz_off(int row, int ch) {
    return (uint32_t)(row * 128 + ((ch ^ (row & 7)) << 4));
}

// tiled global HALF-element offset for (row, col h)
__device__ __forceinline__ size_t tiled_off(size_t row, int h) {
    size_t tile = ((row >> 7) << 4) + (size_t)(h >> 6);
    int r = (int)(row & 127);
    int ch = (h & 63) >> 3;
    return tile * 8192 + (size_t)(r * 64 + ((ch ^ (r & 7)) << 3) + (h & 7));
}

// ---------------------------------------------------------------------------
// fp16 GEMM: D[M,N] = A[M,K] @ W[N,K]^T  (tiled inputs; bulk fills; full/empty
// mbarrier pipeline).
// FUSED=true: grid(24,128), which = x%3 (k/v/r adjacent), fp16 out, and the
//   3rd CTA to finish a (rowblk,colblk) tile runs the WKV elementwise math.
// FUSED=false: grid(8,128), which=3, fp32 out to `outp`.
// ---------------------------------------------------------------------------
template <bool FUSED>
__global__ void __launch_bounds__(256, 2) gemm_mma(
    float* __restrict__ outp,
    const float* __restrict__ aa, const float* __restrict__ bb,
    const float* __restrict__ pp, const float* __restrict__ td,
    const float* __restrict__ tf)
{
    extern __shared__ __align__(1024) char smem[];
    const uint32_t sb = smem_u32(smem);
    const uint32_t fullb = sb;                 // full[s] at sb + s*8
    const uint32_t emptb = sb + 24;            // empty[s] at sb+24 + s*8
    const uint32_t st = sb + SMEM_STAGES_OFF;
    const int tid = threadIdx.x;
    const int lane = tid & 31;
    const int warp = tid >> 5;
    const int wm = warp >> 1;              // 0..3
    const int wn = warp & 1;               // 0..1
    const int m0 = blockIdx.y * BM;
    const int n0 = FUSED ? (blockIdx.x / 3) * BN : blockIdx.x * BN;

    const int which = FUSED ? (blockIdx.x % 3) : 3;
    const __half *A, *B;
    __half* Dh = nullptr;
    if (which == 0)      { A = g_xk; B = g_wk; Dh = g_kh; }
    else if (which == 1) { A = g_xv; B = g_wv; Dh = g_vh; }
    else if (which == 2) { A = g_xr; B = g_wr; Dh = g_rh; }
    else                 { A = g_rw; B = g_wo; }

    float acc[2][8][4];
#pragma unroll
    for (int i = 0; i < 2; i++)
#pragma unroll
        for (int j = 0; j < 8; j++)
#pragma unroll
            for (int l = 0; l < 4; l++) acc[i][j][l] = 0.f;

    if (tid == 0) {
#pragma unroll
        for (int s = 0; s < NSTG; s++) {
            mbar_init(fullb + s * 8, 1);
            mbar_init(emptb + s * 8, 8);
        }
    }
    __syncthreads();

    const size_t a_tile0 = ((size_t)(m0 >> 7)) << 4;   // + chunk
    const size_t b_tile0 = ((size_t)(n0 >> 7)) << 4;

    auto issue_fill = [&](int f) {
        const int s = f % NSTG;
        const uint32_t dst = st + s * STAGE_B;
        mbar_expect_tx(fullb + s * 8, (uint32_t)STAGE_B);
        cp_bulk(dst,           A + (a_tile0 + f) * 8192, PLANE_B, fullb + s * 8);
        cp_bulk(dst + PLANE_B, B + (b_tile0 + f) * 8192, PLANE_B, fullb + s * 8);
    };

    if (tid == 0) { issue_fill(0); issue_fill(1); }

    // ldmatrix lane-address components (proven layout)
    const int lr = lane & 7;
    const int a_row_base = wm * 32 + ((lane >> 3) & 1) * 8 + lr;   // + i*16
    const int a_ch_base  = (lane >> 4);                            // + 2*kk
    const int b_row_base = wn * 64 + (lane >> 4) * 8 + lr;         // + jj*16
    const int b_ch_base  = ((lane >> 3) & 1);                      // + 2*kk

    auto compute = [&](int c) {
        const uint32_t base = st + (c % NSTG) * STAGE_B;
#pragma unroll
        for (int kk = 0; kk < 4; kk++) {
            uint32_t A4[2][4];
            uint32_t B4[2][4];   // ping-pong
#pragma unroll
            for (int i = 0; i < 2; i++) {
                int row = a_row_base + i * 16;
                ldsm4(A4[i], base + swz_off(row, a_ch_base + 2 * kk));
            }
            ldsm4(B4[0], base + PLANE_B + swz_off(b_row_base, b_ch_base + 2 * kk));
#pragma unroll
            for (int jj = 0; jj < 4; jj++) {
                const uint32_t* Bc = B4[jj & 1];
                if (jj < 3) {
                    int rowb = b_row_base + (jj + 1) * 16;
                    ldsm4(B4[(jj + 1) & 1], base + PLANE_B + swz_off(rowb, b_ch_base + 2 * kk));
                }
#pragma unroll
                for (int i = 0; i < 2; i++) {
                    mma_f16(acc[i][2 * jj],     A4[i], Bc[0], Bc[1]);
                    mma_f16(acc[i][2 * jj + 1], A4[i], Bc[2], Bc[3]);
                }
            }
        }
    };

    // ---- pipeline: full/empty barriers, no per-chunk __syncthreads ----
    for (int c = 0; c < NCH; c++) {
        const int s = c % NSTG;
        if (tid == 0) {
            int f = c + 2;
            if (f < NCH) {
                int sf = f % NSTG;
                if (f >= NSTG) {
                    mbar_wait_relaxed(emptb + sf * 8, (uint32_t)(((f / NSTG) + 1) & 1));
                }
                issue_fill(f);
            }
        }
        mbar_wait(fullb + s * 8, (uint32_t)((c / NSTG) & 1));
        compute(c);
        if (lane == 0) mbar_arrive(emptb + s * 8);
    }

    // ---- epilogue ----
#pragma unroll
    for (int i = 0; i < 2; i++) {
        int row = m0 + wm * 32 + i * 16 + (lane >> 2);
#pragma unroll
        for (int j = 0; j < 8; j++) {
            int col = n0 + wn * 64 + j * 8 + (lane & 3) * 2;
            if (FUSED) {
                *(__half2*)(Dh + (size_t)row * HDIM + col) =
                    __floats2half2_rn(acc[i][j][0], acc[i][j][1]);
                *(__half2*)(Dh + (size_t)(row + 8) * HDIM + col) =
                    __floats2half2_rn(acc[i][j][2], acc[i][j][3]);
            } else {
                float2 v0 = { acc[i][j][0], acc[i][j][1] };
                float2 v1 = { acc[i][j][2], acc[i][j][3] };
                *(float2*)(outp + (size_t)row * HDIM + col)       = v0;
                *(float2*)(outp + (size_t)(row + 8) * HDIM + col) = v1;
            }
        }
    }

    // ---- fused WKV elementwise: last CTA of {k,v,r} for this tile runs it ----
    if (FUSED) {
        __threadfence();
        int* flag = (int*)(smem + 64);
        if (tid == 0) {
            int blk = ((m0 >> 7) << 3) + (n0 >> 7);
            int old = atomicAdd(&g_cnt[blk], 1);
            if (old == 2) g_cnt[blk] = 0;   // self-reset for next graph replay
            *flag = old;
        }
        __syncthreads();
        if (*flag == 2) {
            // all three planes for this 128x128 tile are globally visible
#pragma unroll 1
            for (int it = 0; it < 16; it++) {
                int q = it * 256 + tid;       // 0..4095
                int r = q >> 5;               // row within tile
                int cg = q & 31;              // col group (4 elems)
                size_t i = (size_t)(m0 + r) * HDIM + n0 + cg * 4;
                int h = n0 + cg * 4;

                union { uint2 u; __half hh[4]; } KU, VU, RU;
                KU.u = *(const uint2*)(g_kh + i);
                VU.u = *(const uint2*)(g_vh + i);
                RU.u = *(const uint2*)(g_rh + i);

                float4 p4 = *(const float4*)(pp + i);
                float4 a4 = *(const float4*)(aa + i);
                float4 b4 = *(const float4*)(bb + i);
                float4 tf4 = *(const float4*)(tf + h);
                float4 td4 = *(const float4*)(td + h);

                float4 na4, nb4, q24;
                float* p = &p4.x;  float* a = &a4.x;  float* b = &b4.x;
                float* tff = &tf4.x; float* tdd = &td4.x;
                float* na = &na4.x; float* nb = &nb4.x; float* q2 = &q24.x;
                union { __half hh[4]; uint2 u; } RW;

#pragma unroll
                for (int j = 0; j < 4; j++) {
                    float kk = __half2float(KU.hh[j]);
                    float vv = __half2float(VU.hh[j]);
                    float rp = __half2float(RU.hh[j]);
                    float ww = tff[j] + kk;
                    float qq = fmaxf(p[j], ww);
                    float e1 = expf(p[j] - qq);
                    float e2 = expf(ww - qq);
                    float wkv = (e1 * a[j] + e2 * vv) / (e1 * b[j] + e2);
                    float w2 = p[j] + tdd[j];
                    float qb = fmaxf(w2, kk);
                    float e1b = expf(w2 - qb);
                    float e2b = expf(kk - qb);
                    na[j] = e1b * a[j] + e2b * vv;
                    nb[j] = e1b * b[j] + e2b;
                    q2[j] = qb;
                    float rr = 1.f / (1.f + expf(-rp));
                    RW.hh[j] = __float2half_rn(rr * wkv);
                }

                *(uint2*)(g_rw + tiled_off((size_t)(m0 + r), h)) = RW.u;
                *(float4*)(outp + 2 * NBH + i) = na4;  // next_aa
                *(float4*)(outp + 3 * NBH + i) = nb4;  // next_bb
                *(float4*)(outp + 4 * NBH + i) = q24;  // qq2
            }
        }
    }
}

// ---------------------------------------------------------------------------
// prep: blend token-shift mixes -> TILED fp16 planes; copy x -> out slot 1
// ---------------------------------------------------------------------------
__device__ __forceinline__ void blend_store(
    const float4& xv, const float4& av, const float4& m, __half* dst, size_t toff)
{
    union { __half h[4]; uint2 u; } H;
    H.h[0] = __float2half_rn(xv.x * m.x + av.x * (1.f - m.x));
    H.h[1] = __float2half_rn(xv.y * m.y + av.y * (1.f - m.y));
    H.h[2] = __float2half_rn(xv.z * m.z + av.z * (1.f - m.z));
    H.h[3] = __float2half_rn(xv.w * m.w + av.w * (1.f - m.w));
    *(uint2*)(dst + toff) = H.u;
}

__global__ void __launch_bounds__(256) prep_act(
    const float* __restrict__ x, const float* __restrict__ alpha,
    const float* __restrict__ mk, const float* __restrict__ mv,
    const float* __restrict__ mr, float* __restrict__ out)
{
    size_t i = ((size_t)blockIdx.x * 256 + threadIdx.x) * 4;
    int h = (int)(i & (HDIM - 1));
    size_t toff = tiled_off(i >> 10, h);
    float4 xv = *(const float4*)(x + i);
    float4 av = *(const float4*)(alpha + i);
    blend_store(xv, av, *(const float4*)(mk + h), g_xk, toff);
    blend_store(xv, av, *(const float4*)(mv + h), g_xv, toff);
    blend_store(xv, av, *(const float4*)(mr + h), g_xr, toff);
    *(float4*)(out + NBH + i) = xv;   // slot 1: x passthrough
}

__global__ void __launch_bounds__(256) prep_w(
    const float* __restrict__ Wk, const float* __restrict__ Wv,
    const float* __restrict__ Wr, const float* __restrict__ Wo)
{
    const float* W;
    __half* hp;
    switch (blockIdx.y) {
        case 0: W = Wk; hp = g_wk; break;
        case 1: W = Wv; hp = g_wv; break;
        case 2: W = Wr; hp = g_wr; break;
        default: W = Wo; hp = g_wo; break;
    }
    size_t i = ((size_t)blockIdx.x * 256 + threadIdx.x) * 4;
    int h = (int)(i & (HDIM - 1));
    size_t toff = tiled_off(i >> 10, h);
    float4 w = *(const float4*)(W + i);
    union { __half hh[4]; uint2 u; } H;
    H.hh[0] = __float2half_rn(w.x);
    H.hh[1] = __float2half_rn(w.y);
    H.hh[2] = __float2half_rn(w.z);
    H.hh[3] = __float2half_rn(w.w);
    *(uint2*)(hp + toff) = H.u;
}

// ---------------------------------------------------------------------------
extern "C" void kernel_launch(void* const* d_in, const int* in_sizes, int n_in,
                              void* d_out, int out_size)
{
    const float* x     = (const float*)d_in[0];
    const float* alpha = (const float*)d_in[1];
    const float* aa    = (const float*)d_in[2];
    const float* bb    = (const float*)d_in[3];
    const float* pp    = (const float*)d_in[4];
    const float* td    = (const float*)d_in[5];
    const float* tf    = (const float*)d_in[6];
    const float* mk    = (const float*)d_in[7];
    const float* mv    = (const float*)d_in[8];
    const float* mr    = (const float*)d_in[9];
    const float* Wk    = (const float*)d_in[10];
    const float* Wv    = (const float*)d_in[11];
    const float* Wr    = (const float*)d_in[12];
    const float* Wo    = (const float*)d_in[13];
    float* out = (float*)d_out;

    cudaFuncSetAttribute(gemm_mma<true>,  cudaFuncAttributeMaxDynamicSharedMemorySize, SMEM_TOT);
    cudaFuncSetAttribute(gemm_mma<false>, cudaFuncAttributeMaxDynamicSharedMemorySize, SMEM_TOT);

    prep_act<<<(unsigned)(NBH / 1024), 256>>>(x, alpha, mk, mv, mr, out);
    prep_w<<<dim3((unsigned)(NHH / 1024), 4), 256>>>(Wk, Wv, Wr, Wo);

    // k/v/r GEMMs with fused WKV elementwise tail (which = x%3, tiles adjacent)
    gemm_mma<true><<<dim3(24, BDIM / BM), 256, SMEM_TOT>>>(out, aa, bb, pp, td, tf);

    // out = (r*wkv) @ Wo^T
    gemm_mma<false><<<dim3(HDIM / BN, BDIM / BM), 256, SMEM_TOT>>>(out, nullptr, nullptr,
                                                                  nullptr, nullptr, nullptr);
}

// round 15
// speedup vs baseline: 1.0010x; 1.0010x over previous
#include <cuda_runtime.h>
#include <cuda_fp16.h>
#include <cstdint>

#define BDIM 16384
#define HDIM 1024
constexpr size_t NBH = (size_t)BDIM * HDIM;
constexpr size_t NHH = (size_t)HDIM * HDIM;

// ---------------------------------------------------------------------------
// Scratch. GEMM INPUT planes tiled+swizzled (tile = 128x64 = 16 KB,
// ordered [row_blk][k_chunk]); GEMM outputs linear.
// ---------------------------------------------------------------------------
__device__ __align__(16) __half g_kh[NBH];
__device__ __align__(16) __half g_vh[NBH];
__device__ __align__(16) __half g_rh[NBH];

__device__ __align__(16) __half g_xk[NBH];
__device__ __align__(16) __half g_xv[NBH];
__device__ __align__(16) __half g_xr[NBH];
__device__ __align__(16) __half g_rw[NBH];

__device__ __align__(16) __half g_wk[NHH];
__device__ __align__(16) __half g_wv[NHH];
__device__ __align__(16) __half g_wr[NHH];
__device__ __align__(16) __half g_wo[NHH];

// ---------------------------------------------------------------------------
// PTX helpers (sm_90-baseline features only; legal on sm_103 base target)
// ---------------------------------------------------------------------------
__device__ __forceinline__ uint32_t smem_u32(const void* p) {
    uint32_t a;
    asm("{ .reg .u64 t; cvta.to.shared.u64 t, %1; cvt.u32.u64 %0, t; }" : "=r"(a) : "l"(p));
    return a;
}
__device__ __forceinline__ void mbar_init(uint32_t a, uint32_t cnt) {
    asm volatile("mbarrier.init.shared.b64 [%0], %1;" :: "r"(a), "r"(cnt) : "memory");
}
__device__ __forceinline__ void mbar_expect_tx(uint32_t a, uint32_t bytes) {
    asm volatile("mbarrier.arrive.expect_tx.shared.b64 _, [%0], %1;"
                 :: "r"(a), "r"(bytes) : "memory");
}
__device__ __forceinline__ void mbar_arrive(uint32_t a) {
    asm volatile("mbarrier.arrive.shared.b64 _, [%0];" :: "r"(a) : "memory");
}
__device__ __forceinline__ void mbar_wait(uint32_t a, uint32_t parity) {
    asm volatile(
        "{\n\t.reg .pred P;\n\t"
        "WL%=:\n\t"
        "mbarrier.try_wait.parity.acquire.cta.shared::cta.b64 P, [%0], %1, 0x989680;\n\t"
        "@P bra WD%=;\n\t"
        "bra WL%=;\n\t"
        "WD%=:\n\t}"
        :: "r"(a), "r"(parity) : "memory");
}
__device__ __forceinline__ void mbar_wait_relaxed(uint32_t a, uint32_t parity) {
    asm volatile(
        "{\n\t.reg .pred P;\n\t"
        "WL%=:\n\t"
        "mbarrier.try_wait.parity.relaxed.cta.shared::cta.b64 P, [%0], %1, 0x989680;\n\t"
        "@P bra WD%=;\n\t"
        "bra WL%=;\n\t"
        "WD%=:\n\t}"
        :: "r"(a), "r"(parity) : "memory");
}
__device__ __forceinline__ void cp_bulk(uint32_t dst, const void* src, uint32_t bytes,
                                        uint32_t mbar) {
    asm volatile(
        "cp.async.bulk.shared::cluster.global.mbarrier::complete_tx::bytes [%0], [%1], %2, [%3];"
        :: "r"(dst), "l"(src), "r"(bytes), "r"(mbar) : "memory");
}
__device__ __forceinline__ void ldsm4(uint32_t* r, uint32_t addr) {
    asm volatile("ldmatrix.sync.aligned.m8n8.x4.shared.b16 {%0,%1,%2,%3}, [%4];"
                 : "=r"(r[0]), "=r"(r[1]), "=r"(r[2]), "=r"(r[3]) : "r"(addr));
}
__device__ __forceinline__ void mma_f16(float* c, const uint32_t* a, uint32_t b0, uint32_t b1) {
    asm volatile(
        "mma.sync.aligned.m16n8k16.row.col.f32.f16.f16.f32 "
        "{%0,%1,%2,%3}, {%4,%5,%6,%7}, {%8,%9}, {%0,%1,%2,%3};"
        : "+f"(c[0]), "+f"(c[1]), "+f"(c[2]), "+f"(c[3])
        : "r"(a[0]), "r"(a[1]), "r"(a[2]), "r"(a[3]), "r"(b0), "r"(b1));
}

// ---------------------------------------------------------------------------
// GEMM config: CTA tile 128x128x64, 8 warps, 3 stages, PERSISTENT CTAs.
// ---------------------------------------------------------------------------
constexpr int BM = 128, BN = 128, BK = 64;
constexpr int NCH = HDIM / BK;              // 16 chunks per tile
constexpr int NSTG = 3;
constexpr int PLANE_B = BM * BK * 2;        // 16384 bytes (one tile chunk)
constexpr int STAGE_B = 2 * PLANE_B;        // 32768: [A][B]
constexpr int SMEM_STAGES_OFF = 1024;
constexpr int SMEM_TOT = SMEM_STAGES_OFF + NSTG * STAGE_B;  // 99328
constexpr int NCTA = 296;                   // 2 per SM x 148 SMs

__device__ __forceinline__ uint32_t swz_off(int row, int ch) {
    return (uint32_t)(row * 128 + ((ch ^ (row & 7)) << 4));
}

// tiled global HALF-element offset for (row, col h)
__device__ __forceinline__ size_t tiled_off(size_t row, int h) {
    size_t tile = ((row >> 7) << 4) + (size_t)(h >> 6);
    int r = (int)(row & 127);
    int ch = (h & 63) >> 3;
    return tile * 8192 + (size_t)(r * 64 + ((ch ^ (r & 7)) << 3) + (h & 7));
}

// ---------------------------------------------------------------------------
// Persistent fp16 GEMM: D[M,N] = A[M,K] @ W[N,K]^T.
// PH1: 3072 tiles (x=0..23: which=x%3 selects k/v/r; fp16 out).
// !PH1: 1024 tiles (out = rw @ Wo^T, fp32 out).
// One continuous 3-stage bulk-fill pipeline across all tiles of a CTA.
// ---------------------------------------------------------------------------
template <bool PH1>
__global__ void __launch_bounds__(256, 2) gemm_mma(float* __restrict__ outp)
{
    extern __shared__ __align__(1024) char smem[];
    const uint32_t sb = smem_u32(smem);
    const uint32_t fullb = sb;                 // full[s] at sb + s*8
    const uint32_t emptb = sb + 24;            // empty[s] at sb+24 + s*8
    const uint32_t st = sb + SMEM_STAGES_OFF;
    const int tid = threadIdx.x;
    const int lane = tid & 31;
    const int warp = tid >> 5;
    const int wm = warp >> 1;
    const int wn = warp & 1;

    const int NTILE = PH1 ? 3072 : 1024;
    const int t0 = blockIdx.x;
    const int nt_cta = (NTILE - t0 + NCTA - 1) / NCTA;   // tiles for this CTA
    if (nt_cta <= 0) return;
    const int total_q = nt_cta * NCH;

    if (tid == 0) {
#pragma unroll
        for (int s = 0; s < NSTG; s++) {
            mbar_init(fullb + s * 8, 1);
            mbar_init(emptb + s * 8, 8);
        }
    }
    __syncthreads();

    // global-chunk f -> source addresses
    auto issue_fill = [&](int f) {
        const int lt = f >> 4;                  // local tile index
        const int c  = f & 15;                  // chunk within tile
        const int t  = t0 + lt * NCTA;          // global tile
        const __half *A, *B;
        int m_blk, n_blk;
        if (PH1) {
            int x = t % 24;
            m_blk = t / 24;
            n_blk = (x / 3) ^ 0;                // x/3
            n_blk = x / 3;
            int which = x % 3;
            A = (which == 0) ? g_xk : (which == 1) ? g_xv : g_xr;
            B = (which == 0) ? g_wk : (which == 1) ? g_wv : g_wr;
        } else {
            m_blk = t >> 3;
            n_blk = t & 7;
            A = g_rw;
            B = g_wo;
        }
        const int s = f % NSTG;
        const uint32_t dst = st + s * STAGE_B;
        mbar_expect_tx(fullb + s * 8, (uint32_t)STAGE_B);
        cp_bulk(dst,           A + ((size_t)(m_blk * 16 + c)) * 8192, PLANE_B, fullb + s * 8);
        cp_bulk(dst + PLANE_B, B + ((size_t)(n_blk * 16 + c)) * 8192, PLANE_B, fullb + s * 8);
    };

    if (tid == 0) {
        issue_fill(0);
        if (total_q > 1) issue_fill(1);
    }

    // ldmatrix lane-address components (proven layout)
    const int lr = lane & 7;
    const int a_row_base = wm * 32 + ((lane >> 3) & 1) * 8 + lr;
    const int a_ch_base  = (lane >> 4);
    const int b_row_base = wn * 64 + (lane >> 4) * 8 + lr;
    const int b_ch_base  = ((lane >> 3) & 1);

    float acc[2][8][4];
#pragma unroll
    for (int i = 0; i < 2; i++)
#pragma unroll
        for (int j = 0; j < 8; j++)
#pragma unroll
            for (int l = 0; l < 4; l++) acc[i][j][l] = 0.f;

    int q = 0;
#pragma unroll 1
    for (int lt = 0; lt < nt_cta; lt++) {
#pragma unroll 1
        for (int c = 0; c < NCH; c++, q++) {
            const int s = q % NSTG;
            if (tid == 0) {
                int f = q + 2;
                if (f < total_q) {
                    if (f >= NSTG) {
                        mbar_wait_relaxed(emptb + (f % NSTG) * 8,
                                          (uint32_t)(((f / NSTG) + 1) & 1));
                    }
                    issue_fill(f);
                }
            }
            mbar_wait(fullb + s * 8, (uint32_t)((q / NSTG) & 1));

            const uint32_t base = st + s * STAGE_B;
#pragma unroll
            for (int kk = 0; kk < 4; kk++) {
                uint32_t A4[2][4];
                uint32_t B4[2][4];   // ping-pong
#pragma unroll
                for (int i = 0; i < 2; i++) {
                    int row = a_row_base + i * 16;
                    ldsm4(A4[i], base + swz_off(row, a_ch_base + 2 * kk));
                }
                ldsm4(B4[0], base + PLANE_B + swz_off(b_row_base, b_ch_base + 2 * kk));
#pragma unroll
                for (int jj = 0; jj < 4; jj++) {
                    const uint32_t* Bc = B4[jj & 1];
                    if (jj < 3) {
                        int rowb = b_row_base + (jj + 1) * 16;
                        ldsm4(B4[(jj + 1) & 1],
                              base + PLANE_B + swz_off(rowb, b_ch_base + 2 * kk));
                    }
#pragma unroll
                    for (int i = 0; i < 2; i++) {
                        mma_f16(acc[i][2 * jj],     A4[i], Bc[0], Bc[1]);
                        mma_f16(acc[i][2 * jj + 1], A4[i], Bc[2], Bc[3]);
                    }
                }
            }
            if (lane == 0) mbar_arrive(emptb + s * 8);
        }

        // ---- per-tile epilogue (overlaps next tile's in-flight fills) ----
        {
            const int t = t0 + lt * NCTA;
            int m0, n0;
            __half* Dh = nullptr;
            if (PH1) {
                int x = t % 24;
                m0 = (t / 24) * BM;
                n0 = (x / 3) * BN;
                int which = x % 3;
                Dh = (which == 0) ? g_kh : (which == 1) ? g_vh : g_rh;
            } else {
                m0 = (t >> 3) * BM;
                n0 = (t & 7) * BN;
            }
#pragma unroll
            for (int i = 0; i < 2; i++) {
                int row = m0 + wm * 32 + i * 16 + (lane >> 2);
#pragma unroll
                for (int j = 0; j < 8; j++) {
                    int col = n0 + wn * 64 + j * 8 + (lane & 3) * 2;
                    if (PH1) {
                        *(__half2*)(Dh + (size_t)row * HDIM + col) =
                            __floats2half2_rn(acc[i][j][0], acc[i][j][1]);
                        *(__half2*)(Dh + (size_t)(row + 8) * HDIM + col) =
                            __floats2half2_rn(acc[i][j][2], acc[i][j][3]);
                    } else {
                        float2 v0 = { acc[i][j][0], acc[i][j][1] };
                        float2 v1 = { acc[i][j][2], acc[i][j][3] };
                        *(float2*)(outp + (size_t)row * HDIM + col)       = v0;
                        *(float2*)(outp + (size_t)(row + 8) * HDIM + col) = v1;
                    }
                    acc[i][j][0] = 0.f; acc[i][j][1] = 0.f;
                    acc[i][j][2] = 0.f; acc[i][j][3] = 0.f;
                }
            }
        }
    }
}

// ---------------------------------------------------------------------------
// prep: blend token-shift mixes -> TILED fp16 planes; copy x -> out slot 1
// ---------------------------------------------------------------------------
__device__ __forceinline__ void blend_store(
    const float4& xv, const float4& av, const float4& m, __half* dst, size_t toff)
{
    union { __half h[4]; uint2 u; } H;
    H.h[0] = __float2half_rn(xv.x * m.x + av.x * (1.f - m.x));
    H.h[1] = __float2half_rn(xv.y * m.y + av.y * (1.f - m.y));
    H.h[2] = __float2half_rn(xv.z * m.z + av.z * (1.f - m.z));
    H.h[3] = __float2half_rn(xv.w * m.w + av.w * (1.f - m.w));
    *(uint2*)(dst + toff) = H.u;
}

__global__ void __launch_bounds__(256) prep_act(
    const float* __restrict__ x, const float* __restrict__ alpha,
    const float* __restrict__ mk, const float* __restrict__ mv,
    const float* __restrict__ mr, float* __restrict__ out)
{
    size_t i = ((size_t)blockIdx.x * 256 + threadIdx.x) * 4;
    int h = (int)(i & (HDIM - 1));
    size_t toff = tiled_off(i >> 10, h);
    float4 xv = *(const float4*)(x + i);
    float4 av = *(const float4*)(alpha + i);
    blend_store(xv, av, *(const float4*)(mk + h), g_xk, toff);
    blend_store(xv, av, *(const float4*)(mv + h), g_xv, toff);
    blend_store(xv, av, *(const float4*)(mr + h), g_xr, toff);
    *(float4*)(out + NBH + i) = xv;   // slot 1: x passthrough
}

__global__ void __launch_bounds__(256) prep_w(
    const float* __restrict__ Wk, const float* __restrict__ Wv,
    const float* __restrict__ Wr, const float* __restrict__ Wo)
{
    const float* W;
    __half* hp;
    switch (blockIdx.y) {
        case 0: W = Wk; hp = g_wk; break;
        case 1: W = Wv; hp = g_wv; break;
        case 2: W = Wr; hp = g_wr; break;
        default: W = Wo; hp = g_wo; break;
    }
    size_t i = ((size_t)blockIdx.x * 256 + threadIdx.x) * 4;
    int h = (int)(i & (HDIM - 1));
    size_t toff = tiled_off(i >> 10, h);
    float4 w = *(const float4*)(W + i);
    union { __half hh[4]; uint2 u; } H;
    H.hh[0] = __float2half_rn(w.x);
    H.hh[1] = __float2half_rn(w.y);
    H.hh[2] = __float2half_rn(w.z);
    H.hh[3] = __float2half_rn(w.w);
    *(uint2*)(hp + toff) = H.u;
}

// ---------------------------------------------------------------------------
// Fused elementwise WKV + state update + r*wkv (fp16, TILED) + output stores
// ---------------------------------------------------------------------------
__global__ void __launch_bounds__(256) ew_kernel(
    const float* __restrict__ aa, const float* __restrict__ bb,
    const float* __restrict__ pp, const float* __restrict__ td,
    const float* __restrict__ tf, float* __restrict__ out)
{
    size_t i4 = (size_t)blockIdx.x * 256 + threadIdx.x;
    size_t i = i4 * 4;
    int h = (int)(i & (HDIM - 1));

    union { uint2 u; __half hh[4]; } KU, VU, RU;
    KU.u = *(const uint2*)(g_kh + i);
    VU.u = *(const uint2*)(g_vh + i);
    RU.u = *(const uint2*)(g_rh + i);

    float4 p4 = *(const float4*)(pp + i);
    float4 a4 = *(const float4*)(aa + i);
    float4 b4 = *(const float4*)(bb + i);
    float4 tf4 = *(const float4*)(tf + h);
    float4 td4 = *(const float4*)(td + h);

    float4 na4, nb4, q24;
    float* p = &p4.x;  float* a = &a4.x;  float* b = &b4.x;
    float* tff = &tf4.x; float* tdd = &td4.x;
    float* na = &na4.x; float* nb = &nb4.x; float* q2 = &q24.x;

    union { __half hh[4]; uint2 u; } RW;

#pragma unroll
    for (int j = 0; j < 4; j++) {
        float kk = __half2float(KU.hh[j]);
        float vv = __half2float(VU.hh[j]);
        float rp = __half2float(RU.hh[j]);
        float ww = tff[j] + kk;
        float qq = fmaxf(p[j], ww);
        float e1 = expf(p[j] - qq);
        float e2 = expf(ww - qq);
        float wkv = (e1 * a[j] + e2 * vv) / (e1 * b[j] + e2);
        float w2 = p[j] + tdd[j];
        float qb = fmaxf(w2, kk);
        float e1b = expf(w2 - qb);
        float e2b = expf(kk - qb);
        na[j] = e1b * a[j] + e2b * vv;
        nb[j] = e1b * b[j] + e2b;
        q2[j] = qb;
        float r = 1.f / (1.f + expf(-rp));
        RW.hh[j] = __float2half_rn(r * wkv);
    }

    *(uint2*)(g_rw + tiled_off(i >> 10, h)) = RW.u;
    *(float4*)(out + 2 * NBH + i) = na4;  // slot 2: next_aa
    *(float4*)(out + 3 * NBH + i) = nb4;  // slot 3: next_bb
    *(float4*)(out + 4 * NBH + i) = q24;  // slot 4: qq2
}

// ---------------------------------------------------------------------------
extern "C" void kernel_launch(void* const* d_in, const int* in_sizes, int n_in,
                              void* d_out, int out_size)
{
    const float* x     = (const float*)d_in[0];
    const float* alpha = (const float*)d_in[1];
    const float* aa    = (const float*)d_in[2];
    const float* bb    = (const float*)d_in[3];
    const float* pp    = (const float*)d_in[4];
    const float* td    = (const float*)d_in[5];
    const float* tf    = (const float*)d_in[6];
    const float* mk    = (const float*)d_in[7];
    const float* mv    = (const float*)d_in[8];
    const float* mr    = (const float*)d_in[9];
    const float* Wk    = (const float*)d_in[10];
    const float* Wv    = (const float*)d_in[11];
    const float* Wr    = (const float*)d_in[12];
    const float* Wo    = (const float*)d_in[13];
    float* out = (float*)d_out;

    cudaFuncSetAttribute(gemm_mma<true>,  cudaFuncAttributeMaxDynamicSharedMemorySize, SMEM_TOT);
    cudaFuncSetAttribute(gemm_mma<false>, cudaFuncAttributeMaxDynamicSharedMemorySize, SMEM_TOT);

    prep_act<<<(unsigned)(NBH / 1024), 256>>>(x, alpha, mk, mv, mr, out);
    prep_w<<<dim3((unsigned)(NHH / 1024), 4), 256>>>(Wk, Wv, Wr, Wo);

    gemm_mma<true><<<NCTA, 256, SMEM_TOT>>>(out);

    ew_kernel<<<(unsigned)(NBH / 1024), 256>>>(aa, bb, pp, td, tf, out);

    gemm_mma<false><<<NCTA, 256, SMEM_TOT>>>(out);
}

// round 16
// speedup vs baseline: 1.0355x; 1.0344x over previous
#include <cuda_runtime.h>
#include <cuda_fp16.h>
#include <cstdint>

#define BDIM 16384
#define HDIM 1024
constexpr size_t NBH = (size_t)BDIM * HDIM;
constexpr size_t NHH = (size_t)HDIM * HDIM;

// ---------------------------------------------------------------------------
// Scratch. GEMM INPUT planes tiled+swizzled (tile = 128x64 = 16 KB,
// ordered [row_blk][k_chunk]); GEMM outputs linear.
// ---------------------------------------------------------------------------
__device__ __align__(16) __half g_kh[NBH];
__device__ __align__(16) __half g_vh[NBH];
__device__ __align__(16) __half g_rh[NBH];

__device__ __align__(16) __half g_xk[NBH];
__device__ __align__(16) __half g_xv[NBH];
__device__ __align__(16) __half g_xr[NBH];
__device__ __align__(16) __half g_rw[NBH];

__device__ __align__(16) __half g_wk[NHH];
__device__ __align__(16) __half g_wv[NHH];
__device__ __align__(16) __half g_wr[NHH];
__device__ __align__(16) __half g_wo[NHH];

// ---------------------------------------------------------------------------
// PTX helpers (sm_90-baseline features only; legal on sm_103 base target)
// ---------------------------------------------------------------------------
__device__ __forceinline__ uint32_t smem_u32(const void* p) {
    uint32_t a;
    asm("{ .reg .u64 t; cvta.to.shared.u64 t, %1; cvt.u32.u64 %0, t; }" : "=r"(a) : "l"(p));
    return a;
}
__device__ __forceinline__ void mbar_init(uint32_t a, uint32_t cnt) {
    asm volatile("mbarrier.init.shared.b64 [%0], %1;" :: "r"(a), "r"(cnt) : "memory");
}
__device__ __forceinline__ void mbar_expect_tx(uint32_t a, uint32_t bytes) {
    asm volatile("mbarrier.arrive.expect_tx.shared.b64 _, [%0], %1;"
                 :: "r"(a), "r"(bytes) : "memory");
}
__device__ __forceinline__ void mbar_arrive(uint32_t a) {
    asm volatile("mbarrier.arrive.shared.b64 _, [%0];" :: "r"(a) : "memory");
}
__device__ __forceinline__ void mbar_wait(uint32_t a, uint32_t parity) {
    asm volatile(
        "{\n\t.reg .pred P;\n\t"
        "WL%=:\n\t"
        "mbarrier.try_wait.parity.acquire.cta.shared::cta.b64 P, [%0], %1, 0x989680;\n\t"
        "@P bra WD%=;\n\t"
        "bra WL%=;\n\t"
        "WD%=:\n\t}"
        :: "r"(a), "r"(parity) : "memory");
}
__device__ __forceinline__ void mbar_wait_relaxed(uint32_t a, uint32_t parity) {
    asm volatile(
        "{\n\t.reg .pred P;\n\t"
        "WL%=:\n\t"
        "mbarrier.try_wait.parity.relaxed.cta.shared::cta.b64 P, [%0], %1, 0x989680;\n\t"
        "@P bra WD%=;\n\t"
        "bra WL%=;\n\t"
        "WD%=:\n\t}"
        :: "r"(a), "r"(parity) : "memory");
}
__device__ __forceinline__ void cp_bulk(uint32_t dst, const void* src, uint32_t bytes,
                                        uint32_t mbar) {
    asm volatile(
        "cp.async.bulk.shared::cluster.global.mbarrier::complete_tx::bytes [%0], [%1], %2, [%3];"
        :: "r"(dst), "l"(src), "r"(bytes), "r"(mbar) : "memory");
}
__device__ __forceinline__ void ldsm4(uint32_t* r, uint32_t addr) {
    asm volatile("ldmatrix.sync.aligned.m8n8.x4.shared.b16 {%0,%1,%2,%3}, [%4];"
                 : "=r"(r[0]), "=r"(r[1]), "=r"(r[2]), "=r"(r[3]) : "r"(addr));
}
__device__ __forceinline__ void mma_f16(float* c, const uint32_t* a, uint32_t b0, uint32_t b1) {
    asm volatile(
        "mma.sync.aligned.m16n8k16.row.col.f32.f16.f16.f32 "
        "{%0,%1,%2,%3}, {%4,%5,%6,%7}, {%8,%9}, {%0,%1,%2,%3};"
        : "+f"(c[0]), "+f"(c[1]), "+f"(c[2]), "+f"(c[3])
        : "r"(a[0]), "r"(a[1]), "r"(a[2]), "r"(a[3]), "r"(b0), "r"(b1));
}

// ---------------------------------------------------------------------------
// GEMM config: CTA 128x128x64, 4 warps (2m x 2n -> warp tile 64x64), 3 stages
// 128 threads/CTA, 2 CTAs/SM -> 256 regs/thread budget (acc=128 fits, no spill)
// ---------------------------------------------------------------------------
constexpr int BM = 128, BN = 128, BK = 64;
constexpr int GT = 128;                     // threads per CTA
constexpr int NCH = HDIM / BK;              // 16
constexpr int NSTG = 3;
constexpr int PLANE_B = BM * BK * 2;        // 16384 bytes (one tile)
constexpr int STAGE_B = 2 * PLANE_B;        // 32768: [A][B]
constexpr int SMEM_STAGES_OFF = 1024;
constexpr int SMEM_TOT = SMEM_STAGES_OFF + NSTG * STAGE_B;  // 99328

__device__ __forceinline__ uint32_t swz_off(int row, int ch) {
    return (uint32_t)(row * 128 + ((ch ^ (row & 7)) << 4));
}

// tiled global HALF-element offset for (row, col h)
__device__ __forceinline__ size_t tiled_off(size_t row, int h) {
    size_t tile = ((row >> 7) << 4) + (size_t)(h >> 6);
    int r = (int)(row & 127);
    int ch = (h & 63) >> 3;
    return tile * 8192 + (size_t)(r * 64 + ((ch ^ (r & 7)) << 3) + (h & 7));
}

// ---------------------------------------------------------------------------
// fp16 GEMM: D[M,N] = A[M,K] @ W[N,K]^T  (tiled inputs; bulk fills; full/empty
// mbarrier pipeline; 64x64 warp tiles).
// which = base + blockIdx.z: 0=k, 1=v, 2=r (fp16 out), 3=out (fp32 out)
// ---------------------------------------------------------------------------
template <bool FP16OUT>
__global__ void __launch_bounds__(GT, 2) gemm_mma(int base_which, float* __restrict__ outp)
{
    extern __shared__ __align__(1024) char smem[];
    const uint32_t sb = smem_u32(smem);
    const uint32_t fullb = sb;                 // full[s] at sb + s*8
    const uint32_t emptb = sb + 24;            // empty[s] at sb+24 + s*8
    const uint32_t st = sb + SMEM_STAGES_OFF;
    const int tid = threadIdx.x;
    const int lane = tid & 31;
    const int warp = tid >> 5;                 // 0..3
    const int wm = warp >> 1;                  // 0..1 (64-row slice)
    const int wn = warp & 1;                   // 0..1 (64-col slice)
    const int m0 = blockIdx.y * BM;
    const int n0 = blockIdx.x * BN;

    const int which = base_which + blockIdx.z;
    const __half *A, *B;
    __half* Dh = nullptr;
    if (which == 0)      { A = g_xk; B = g_wk; Dh = g_kh; }
    else if (which == 1) { A = g_xv; B = g_wv; Dh = g_vh; }
    else if (which == 2) { A = g_xr; B = g_wr; Dh = g_rh; }
    else                 { A = g_rw; B = g_wo; }

    float acc[4][8][4];
#pragma unroll
    for (int i = 0; i < 4; i++)
#pragma unroll
        for (int j = 0; j < 8; j++)
#pragma unroll
            for (int l = 0; l < 4; l++) acc[i][j][l] = 0.f;

    if (tid == 0) {
#pragma unroll
        for (int s = 0; s < NSTG; s++) {
            mbar_init(fullb + s * 8, 1);
            mbar_init(emptb + s * 8, 4);       // 4 warps arrive
        }
    }
    __syncthreads();

    const size_t a_tile0 = ((size_t)(m0 >> 7)) << 4;   // + chunk
    const size_t b_tile0 = ((size_t)(n0 >> 7)) << 4;

    auto issue_fill = [&](int f) {
        const int s = f % NSTG;
        const uint32_t dst = st + s * STAGE_B;
        mbar_expect_tx(fullb + s * 8, (uint32_t)STAGE_B);
        cp_bulk(dst,           A + (a_tile0 + f) * 8192, PLANE_B, fullb + s * 8);
        cp_bulk(dst + PLANE_B, B + (b_tile0 + f) * 8192, PLANE_B, fullb + s * 8);
    };

    if (tid == 0) { issue_fill(0); issue_fill(1); }

    // ldmatrix lane-address components (64x64 warp tile)
    const int lr = lane & 7;
    const int a_row_base = wm * 64 + ((lane >> 3) & 1) * 8 + lr;   // + i*16, i<4
    const int a_ch_base  = (lane >> 4);                            // + 2*kk
    const int b_row_base = wn * 64 + (lane >> 4) * 8 + lr;         // + jj*16, jj<4
    const int b_ch_base  = ((lane >> 3) & 1);                      // + 2*kk

    auto compute = [&](int c) {
        const uint32_t base = st + (c % NSTG) * STAGE_B;
#pragma unroll
        for (int kk = 0; kk < 4; kk++) {
            uint32_t A4[4][4];
            uint32_t B4[2][4];   // ping-pong
#pragma unroll
            for (int i = 0; i < 4; i++) {
                int row = a_row_base + i * 16;
                ldsm4(A4[i], base + swz_off(row, a_ch_base + 2 * kk));
            }
            ldsm4(B4[0], base + PLANE_B + swz_off(b_row_base, b_ch_base + 2 * kk));
#pragma unroll
            for (int jj = 0; jj < 4; jj++) {
                const uint32_t* Bc = B4[jj & 1];
                if (jj < 3) {
                    int rowb = b_row_base + (jj + 1) * 16;
                    ldsm4(B4[(jj + 1) & 1],
                          base + PLANE_B + swz_off(rowb, b_ch_base + 2 * kk));
                }
#pragma unroll
                for (int i = 0; i < 4; i++) {
                    mma_f16(acc[i][2 * jj],     A4[i], Bc[0], Bc[1]);
                    mma_f16(acc[i][2 * jj + 1], A4[i], Bc[2], Bc[3]);
                }
            }
        }
    };

    // ---- pipeline: full/empty barriers ----
    for (int c = 0; c < NCH; c++) {
        const int s = c % NSTG;
        if (tid == 0) {
            int f = c + 2;
            if (f < NCH) {
                int sf = f % NSTG;
                if (f >= NSTG) {
                    mbar_wait_relaxed(emptb + sf * 8, (uint32_t)(((f / NSTG) + 1) & 1));
                }
                issue_fill(f);
            }
        }
        mbar_wait(fullb + s * 8, (uint32_t)((c / NSTG) & 1));
        compute(c);
        if (lane == 0) mbar_arrive(emptb + s * 8);
    }

    // ---- epilogue ----
#pragma unroll
    for (int i = 0; i < 4; i++) {
        int row = m0 + wm * 64 + i * 16 + (lane >> 2);
#pragma unroll
        for (int j = 0; j < 8; j++) {
            int col = n0 + wn * 64 + j * 8 + (lane & 3) * 2;
            if (FP16OUT) {
                *(__half2*)(Dh + (size_t)row * HDIM + col) =
                    __floats2half2_rn(acc[i][j][0], acc[i][j][1]);
                *(__half2*)(Dh + (size_t)(row + 8) * HDIM + col) =
                    __floats2half2_rn(acc[i][j][2], acc[i][j][3]);
            } else {
                float2 v0 = { acc[i][j][0], acc[i][j][1] };
                float2 v1 = { acc[i][j][2], acc[i][j][3] };
                *(float2*)(outp + (size_t)row * HDIM + col)       = v0;
                *(float2*)(outp + (size_t)(row + 8) * HDIM + col) = v1;
            }
        }
    }
}

// ---------------------------------------------------------------------------
// prep: blend token-shift mixes -> TILED fp16 planes; copy x -> out slot 1
// ---------------------------------------------------------------------------
__device__ __forceinline__ void blend_store(
    const float4& xv, const float4& av, const float4& m, __half* dst, size_t toff)
{
    union { __half h[4]; uint2 u; } H;
    H.h[0] = __float2half_rn(xv.x * m.x + av.x * (1.f - m.x));
    H.h[1] = __float2half_rn(xv.y * m.y + av.y * (1.f - m.y));
    H.h[2] = __float2half_rn(xv.z * m.z + av.z * (1.f - m.z));
    H.h[3] = __float2half_rn(xv.w * m.w + av.w * (1.f - m.w));
    *(uint2*)(dst + toff) = H.u;
}

__global__ void __launch_bounds__(256) prep_act(
    const float* __restrict__ x, const float* __restrict__ alpha,
    const float* __restrict__ mk, const float* __restrict__ mv,
    const float* __restrict__ mr, float* __restrict__ out)
{
    size_t i = ((size_t)blockIdx.x * 256 + threadIdx.x) * 4;
    int h = (int)(i & (HDIM - 1));
    size_t toff = tiled_off(i >> 10, h);
    float4 xv = *(const float4*)(x + i);
    float4 av = *(const float4*)(alpha + i);
    blend_store(xv, av, *(const float4*)(mk + h), g_xk, toff);
    blend_store(xv, av, *(const float4*)(mv + h), g_xv, toff);
    blend_store(xv, av, *(const float4*)(mr + h), g_xr, toff);
    *(float4*)(out + NBH + i) = xv;   // slot 1: x passthrough
}

__global__ void __launch_bounds__(256) prep_w(
    const float* __restrict__ Wk, const float* __restrict__ Wv,
    const float* __restrict__ Wr, const float* __restrict__ Wo)
{
    const float* W;
    __half* hp;
    switch (blockIdx.y) {
        case 0: W = Wk; hp = g_wk; break;
        case 1: W = Wv; hp = g_wv; break;
        case 2: W = Wr; hp = g_wr; break;
        default: W = Wo; hp = g_wo; break;
    }
    size_t i = ((size_t)blockIdx.x * 256 + threadIdx.x) * 4;
    int h = (int)(i & (HDIM - 1));
    size_t toff = tiled_off(i >> 10, h);
    float4 w = *(const float4*)(W + i);
    union { __half hh[4]; uint2 u; } H;
    H.hh[0] = __float2half_rn(w.x);
    H.hh[1] = __float2half_rn(w.y);
    H.hh[2] = __float2half_rn(w.z);
    H.hh[3] = __float2half_rn(w.w);
    *(uint2*)(hp + toff) = H.u;
}

// ---------------------------------------------------------------------------
// Fused elementwise WKV + state update + r*wkv (fp16, TILED) + output stores
// ---------------------------------------------------------------------------
__global__ void __launch_bounds__(256) ew_kernel(
    const float* __restrict__ aa, const float* __restrict__ bb,
    const float* __restrict__ pp, const float* __restrict__ td,
    const float* __restrict__ tf, float* __restrict__ out)
{
    size_t i4 = (size_t)blockIdx.x * 256 + threadIdx.x;
    size_t i = i4 * 4;
    int h = (int)(i & (HDIM - 1));

    union { uint2 u; __half hh[4]; } KU, VU, RU;
    KU.u = *(const uint2*)(g_kh + i);
    VU.u = *(const uint2*)(g_vh + i);
    RU.u = *(const uint2*)(g_rh + i);

    float4 p4 = *(const float4*)(pp + i);
    float4 a4 = *(const float4*)(aa + i);
    float4 b4 = *(const float4*)(bb + i);
    float4 tf4 = *(const float4*)(tf + h);
    float4 td4 = *(const float4*)(td + h);

    float4 na4, nb4, q24;
    float* p = &p4.x;  float* a = &a4.x;  float* b = &b4.x;
    float* tff = &tf4.x; float* tdd = &td4.x;
    float* na = &na4.x; float* nb = &nb4.x; float* q2 = &q24.x;

    union { __half hh[4]; uint2 u; } RW;

#pragma unroll
    for (int j = 0; j < 4; j++) {
        float kk = __half2float(KU.hh[j]);
        float vv = __half2float(VU.hh[j]);
        float rp = __half2float(RU.hh[j]);
        float ww = tff[j] + kk;
        float qq = fmaxf(p[j], ww);
        float e1 = expf(p[j] - qq);
        float e2 = expf(ww - qq);
        float wkv = (e1 * a[j] + e2 * vv) / (e1 * b[j] + e2);
        float w2 = p[j] + tdd[j];
        float qb = fmaxf(w2, kk);
        float e1b = expf(w2 - qb);
        float e2b = expf(kk - qb);
        na[j] = e1b * a[j] + e2b * vv;
        nb[j] = e1b * b[j] + e2b;
        q2[j] = qb;
        float r = 1.f / (1.f + expf(-rp));
        RW.hh[j] = __float2half_rn(r * wkv);
    }

    *(uint2*)(g_rw + tiled_off(i >> 10, h)) = RW.u;
    *(float4*)(out + 2 * NBH + i) = na4;  // slot 2: next_aa
    *(float4*)(out + 3 * NBH + i) = nb4;  // slot 3: next_bb
    *(float4*)(out + 4 * NBH + i) = q24;  // slot 4: qq2
}

// ---------------------------------------------------------------------------
extern "C" void kernel_launch(void* const* d_in, const int* in_sizes, int n_in,
                              void* d_out, int out_size)
{
    const float* x     = (const float*)d_in[0];
    const float* alpha = (const float*)d_in[1];
    const float* aa    = (const float*)d_in[2];
    const float* bb    = (const float*)d_in[3];
    const float* pp    = (const float*)d_in[4];
    const float* td    = (const float*)d_in[5];
    const float* tf    = (const float*)d_in[6];
    const float* mk    = (const float*)d_in[7];
    const float* mv    = (const float*)d_in[8];
    const float* mr    = (const float*)d_in[9];
    const float* Wk    = (const float*)d_in[10];
    const float* Wv    = (const float*)d_in[11];
    const float* Wr    = (const float*)d_in[12];
    const float* Wo    = (const float*)d_in[13];
    float* out = (float*)d_out;

    cudaFuncSetAttribute(gemm_mma<true>,  cudaFuncAttributeMaxDynamicSharedMemorySize, SMEM_TOT);
    cudaFuncSetAttribute(gemm_mma<false>, cudaFuncAttributeMaxDynamicSharedMemorySize, SMEM_TOT);

    prep_act<<<(unsigned)(NBH / 1024), 256>>>(x, alpha, mk, mv, mr, out);
    prep_w<<<dim3((unsigned)(NHH / 1024), 4), 256>>>(Wk, Wv, Wr, Wo);

    dim3 g3(HDIM / BN, BDIM / BM, 3);
    gemm_mma<true><<<g3, GT, SMEM_TOT>>>(0, nullptr);

    ew_kernel<<<(unsigned)(NBH / 1024), 256>>>(aa, bb, pp, td, tf, out);

    dim3 g1(HDIM / BN, BDIM / BM, 1);
    gemm_mma<false><<<g1, GT, SMEM_TOT>>>(3, out);
}

// round 17
// speedup vs baseline: 1.0356x; 1.0002x over previous
#include <cuda_runtime.h>
#include <cuda_fp16.h>
#include <cstdint>

#define BDIM 16384
#define HDIM 1024
constexpr size_t NBH = (size_t)BDIM * HDIM;
constexpr size_t NHH = (size_t)HDIM * HDIM;

// ---------------------------------------------------------------------------
// Scratch. GEMM INPUT planes tiled+swizzled (tile = 128x64 = 16 KB,
// ordered [row_blk][k_chunk]); GEMM outputs linear.
// ---------------------------------------------------------------------------
__device__ __align__(16) __half g_kh[NBH];
__device__ __align__(16) __half g_vh[NBH];
__device__ __align__(16) __half g_rh[NBH];

__device__ __align__(16) __half g_xk[NBH];
__device__ __align__(16) __half g_xv[NBH];
__device__ __align__(16) __half g_xr[NBH];
__device__ __align__(16) __half g_rw[NBH];

__device__ __align__(16) __half g_wk[NHH];
__device__ __align__(16) __half g_wv[NHH];
__device__ __align__(16) __half g_wr[NHH];
__device__ __align__(16) __half g_wo[NHH];

// ---------------------------------------------------------------------------
// PTX helpers (sm_90-baseline features only; legal on sm_103 base target)
// ---------------------------------------------------------------------------
__device__ __forceinline__ uint32_t smem_u32(const void* p) {
    uint32_t a;
    asm("{ .reg .u64 t; cvta.to.shared.u64 t, %1; cvt.u32.u64 %0, t; }" : "=r"(a) : "l"(p));
    return a;
}
__device__ __forceinline__ void mbar_init(uint32_t a, uint32_t cnt) {
    asm volatile("mbarrier.init.shared.b64 [%0], %1;" :: "r"(a), "r"(cnt) : "memory");
}
__device__ __forceinline__ void mbar_expect_tx(uint32_t a, uint32_t bytes) {
    asm volatile("mbarrier.arrive.expect_tx.shared.b64 _, [%0], %1;"
                 :: "r"(a), "r"(bytes) : "memory");
}
__device__ __forceinline__ void mbar_arrive(uint32_t a) {
    asm volatile("mbarrier.arrive.shared.b64 _, [%0];" :: "r"(a) : "memory");
}
__device__ __forceinline__ void mbar_wait(uint32_t a, uint32_t parity) {
    asm volatile(
        "{\n\t.reg .pred P;\n\t"
        "WL%=:\n\t"
        "mbarrier.try_wait.parity.acquire.cta.shared::cta.b64 P, [%0], %1, 0x989680;\n\t"
        "@P bra WD%=;\n\t"
        "bra WL%=;\n\t"
        "WD%=:\n\t}"
        :: "r"(a), "r"(parity) : "memory");
}
__device__ __forceinline__ void mbar_wait_relaxed(uint32_t a, uint32_t parity) {
    asm volatile(
        "{\n\t.reg .pred P;\n\t"
        "WL%=:\n\t"
        "mbarrier.try_wait.parity.relaxed.cta.shared::cta.b64 P, [%0], %1, 0x989680;\n\t"
        "@P bra WD%=;\n\t"
        "bra WL%=;\n\t"
        "WD%=:\n\t}"
        :: "r"(a), "r"(parity) : "memory");
}
__device__ __forceinline__ void cp_bulk(uint32_t dst, const void* src, uint32_t bytes,
                                        uint32_t mbar) {
    asm volatile(
        "cp.async.bulk.shared::cluster.global.mbarrier::complete_tx::bytes [%0], [%1], %2, [%3];"
        :: "r"(dst), "l"(src), "r"(bytes), "r"(mbar) : "memory");
}
__device__ __forceinline__ void ldsm4(uint32_t* r, uint32_t addr) {
    asm volatile("ldmatrix.sync.aligned.m8n8.x4.shared.b16 {%0,%1,%2,%3}, [%4];"
                 : "=r"(r[0]), "=r"(r[1]), "=r"(r[2]), "=r"(r[3]) : "r"(addr));
}
__device__ __forceinline__ void mma_f16(float* c, const uint32_t* a, uint32_t b0, uint32_t b1) {
    asm volatile(
        "mma.sync.aligned.m16n8k16.row.col.f32.f16.f16.f32 "
        "{%0,%1,%2,%3}, {%4,%5,%6,%7}, {%8,%9}, {%0,%1,%2,%3};"
        : "+f"(c[0]), "+f"(c[1]), "+f"(c[2]), "+f"(c[3])
        : "r"(a[0]), "r"(a[1]), "r"(a[2]), "r"(a[3]), "r"(b0), "r"(b1));
}

// ---------------------------------------------------------------------------
// GEMM config: CTA 128x128x64, 4 warps (2m x 2n -> warp tile 64x64), 3 stages
// 128 threads/CTA, 2 CTAs/SM -> 256 regs/thread budget
// ---------------------------------------------------------------------------
constexpr int BM = 128, BN = 128, BK = 64;
constexpr int GT = 128;                     // threads per CTA
constexpr int NCH = HDIM / BK;              // 16
constexpr int NSTG = 3;
constexpr int PLANE_B = BM * BK * 2;        // 16384 bytes (one tile)
constexpr int STAGE_B = 2 * PLANE_B;        // 32768: [A][B]
constexpr int SMEM_STAGES_OFF = 1024;
constexpr int SMEM_TOT = SMEM_STAGES_OFF + NSTG * STAGE_B;  // 99328

__device__ __forceinline__ uint32_t swz_off(int row, int ch) {
    return (uint32_t)(row * 128 + ((ch ^ (row & 7)) << 4));
}

// tiled global HALF-element offset for (row, col h)
__device__ __forceinline__ size_t tiled_off(size_t row, int h) {
    size_t tile = ((row >> 7) << 4) + (size_t)(h >> 6);
    int r = (int)(row & 127);
    int ch = (h & 63) >> 3;
    return tile * 8192 + (size_t)(r * 64 + ((ch ^ (r & 7)) << 3) + (h & 7));
}

// ---------------------------------------------------------------------------
// fp16 GEMM: D[M,N] = A[M,K] @ W[N,K]^T  (tiled inputs; bulk fills; full/empty
// mbarrier pipeline; 64x64 warp tiles; per-kk grouped loads + early release).
// which = base + blockIdx.z: 0=k, 1=v, 2=r (fp16 out), 3=out (fp32 out)
// ---------------------------------------------------------------------------
template <bool FP16OUT>
__global__ void __launch_bounds__(GT, 2) gemm_mma(int base_which, float* __restrict__ outp)
{
    extern __shared__ __align__(1024) char smem[];
    const uint32_t sb = smem_u32(smem);
    const uint32_t fullb = sb;                 // full[s] at sb + s*8
    const uint32_t emptb = sb + 24;            // empty[s] at sb+24 + s*8
    const uint32_t st = sb + SMEM_STAGES_OFF;
    const int tid = threadIdx.x;
    const int lane = tid & 31;
    const int warp = tid >> 5;                 // 0..3
    const int wm = warp >> 1;                  // 0..1 (64-row slice)
    const int wn = warp & 1;                   // 0..1 (64-col slice)
    const int m0 = blockIdx.y * BM;
    const int n0 = blockIdx.x * BN;

    const int which = base_which + blockIdx.z;
    const __half *A, *B;
    __half* Dh = nullptr;
    if (which == 0)      { A = g_xk; B = g_wk; Dh = g_kh; }
    else if (which == 1) { A = g_xv; B = g_wv; Dh = g_vh; }
    else if (which == 2) { A = g_xr; B = g_wr; Dh = g_rh; }
    else                 { A = g_rw; B = g_wo; }

    float acc[4][8][4];
#pragma unroll
    for (int i = 0; i < 4; i++)
#pragma unroll
        for (int j = 0; j < 8; j++)
#pragma unroll
            for (int l = 0; l < 4; l++) acc[i][j][l] = 0.f;

    if (tid == 0) {
#pragma unroll
        for (int s = 0; s < NSTG; s++) {
            mbar_init(fullb + s * 8, 1);
            mbar_init(emptb + s * 8, 4);       // 4 warps arrive
        }
    }
    __syncthreads();

    const size_t a_tile0 = ((size_t)(m0 >> 7)) << 4;   // + chunk
    const size_t b_tile0 = ((size_t)(n0 >> 7)) << 4;

    auto issue_fill = [&](int f) {
        const int s = f % NSTG;
        const uint32_t dst = st + s * STAGE_B;
        mbar_expect_tx(fullb + s * 8, (uint32_t)STAGE_B);
        cp_bulk(dst,           A + (a_tile0 + f) * 8192, PLANE_B, fullb + s * 8);
        cp_bulk(dst + PLANE_B, B + (b_tile0 + f) * 8192, PLANE_B, fullb + s * 8);
    };

    if (tid == 0) { issue_fill(0); issue_fill(1); }

    // ldmatrix lane-address components (64x64 warp tile)
    const int lr = lane & 7;
    const int a_row_base = wm * 64 + ((lane >> 3) & 1) * 8 + lr;   // + i*16, i<4
    const int a_ch_base  = (lane >> 4);                            // + 2*kk
    const int b_row_base = wn * 64 + (lane >> 4) * 8 + lr;         // + jj*16, jj<4
    const int b_ch_base  = ((lane >> 3) & 1);                      // + 2*kk

    // ---- pipeline: full/empty barriers ----
    for (int c = 0; c < NCH; c++) {
        const int s = c % NSTG;
        if (tid == 0) {
            int f = c + 2;
            if (f < NCH) {
                int sf = f % NSTG;
                if (f >= NSTG) {
                    mbar_wait_relaxed(emptb + sf * 8, (uint32_t)(((f / NSTG) + 1) & 1));
                }
                issue_fill(f);
            }
        }
        mbar_wait(fullb + s * 8, (uint32_t)((c / NSTG) & 1));

        const uint32_t base = st + s * STAGE_B;
#pragma unroll
        for (int kk = 0; kk < 4; kk++) {
            uint32_t A4[4][4];
            uint32_t B4[4][4];
#pragma unroll
            for (int i = 0; i < 4; i++) {
                int row = a_row_base + i * 16;
                ldsm4(A4[i], base + swz_off(row, a_ch_base + 2 * kk));
            }
#pragma unroll
            for (int jj = 0; jj < 4; jj++) {
                int rowb = b_row_base + jj * 16;
                ldsm4(B4[jj], base + PLANE_B + swz_off(rowb, b_ch_base + 2 * kk));
            }
            // last smem read of this stage done -> release it early
            if (kk == 3 && lane == 0) mbar_arrive(emptb + s * 8);
#pragma unroll
            for (int jj = 0; jj < 4; jj++)
#pragma unroll
                for (int i = 0; i < 4; i++) {
                    mma_f16(acc[i][2 * jj],     A4[i], B4[jj][0], B4[jj][1]);
                    mma_f16(acc[i][2 * jj + 1], A4[i], B4[jj][2], B4[jj][3]);
                }
        }
    }

    // ---- epilogue ----
#pragma unroll
    for (int i = 0; i < 4; i++) {
        int row = m0 + wm * 64 + i * 16 + (lane >> 2);
#pragma unroll
        for (int j = 0; j < 8; j++) {
            int col = n0 + wn * 64 + j * 8 + (lane & 3) * 2;
            if (FP16OUT) {
                *(__half2*)(Dh + (size_t)row * HDIM + col) =
                    __floats2half2_rn(acc[i][j][0], acc[i][j][1]);
                *(__half2*)(Dh + (size_t)(row + 8) * HDIM + col) =
                    __floats2half2_rn(acc[i][j][2], acc[i][j][3]);
            } else {
                float2 v0 = { acc[i][j][0], acc[i][j][1] };
                float2 v1 = { acc[i][j][2], acc[i][j][3] };
                *(float2*)(outp + (size_t)row * HDIM + col)       = v0;
                *(float2*)(outp + (size_t)(row + 8) * HDIM + col) = v1;
            }
        }
    }
}

// ---------------------------------------------------------------------------
// prep: blend token-shift mixes -> TILED fp16 planes; copy x -> out slot 1
// ---------------------------------------------------------------------------
__device__ __forceinline__ void blend_store(
    const float4& xv, const float4& av, const float4& m, __half* dst, size_t toff)
{
    union { __half h[4]; uint2 u; } H;
    H.h[0] = __float2half_rn(xv.x * m.x + av.x * (1.f - m.x));
    H.h[1] = __float2half_rn(xv.y * m.y + av.y * (1.f - m.y));
    H.h[2] = __float2half_rn(xv.z * m.z + av.z * (1.f - m.z));
    H.h[3] = __float2half_rn(xv.w * m.w + av.w * (1.f - m.w));
    *(uint2*)(dst + toff) = H.u;
}

__global__ void __launch_bounds__(256) prep_act(
    const float* __restrict__ x, const float* __restrict__ alpha,
    const float* __restrict__ mk, const float* __restrict__ mv,
    const float* __restrict__ mr, float* __restrict__ out)
{
    size_t i = ((size_t)blockIdx.x * 256 + threadIdx.x) * 4;
    int h = (int)(i & (HDIM - 1));
    size_t toff = tiled_off(i >> 10, h);
    float4 xv = *(const float4*)(x + i);
    float4 av = *(const float4*)(alpha + i);
    blend_store(xv, av, *(const float4*)(mk + h), g_xk, toff);
    blend_store(xv, av, *(const float4*)(mv + h), g_xv, toff);
    blend_store(xv, av, *(const float4*)(mr + h), g_xr, toff);
    *(float4*)(out + NBH + i) = xv;   // slot 1: x passthrough
}

__global__ void __launch_bounds__(256) prep_w(
    const float* __restrict__ Wk, const float* __restrict__ Wv,
    const float* __restrict__ Wr, const float* __restrict__ Wo)
{
    const float* W;
    __half* hp;
    switch (blockIdx.y) {
        case 0: W = Wk; hp = g_wk; break;
        case 1: W = Wv; hp = g_wv; break;
        case 2: W = Wr; hp = g_wr; break;
        default: W = Wo; hp = g_wo; break;
    }
    size_t i = ((size_t)blockIdx.x * 256 + threadIdx.x) * 4;
    int h = (int)(i & (HDIM - 1));
    size_t toff = tiled_off(i >> 10, h);
    float4 w = *(const float4*)(W + i);
    union { __half hh[4]; uint2 u; } H;
    H.hh[0] = __float2half_rn(w.x);
    H.hh[1] = __float2half_rn(w.y);
    H.hh[2] = __float2half_rn(w.z);
    H.hh[3] = __float2half_rn(w.w);
    *(uint2*)(hp + toff) = H.u;
}

// ---------------------------------------------------------------------------
// Fused elementwise WKV + state update + r*wkv (fp16, TILED) + output stores
// ---------------------------------------------------------------------------
__global__ void __launch_bounds__(256) ew_kernel(
    const float* __restrict__ aa, const float* __restrict__ bb,
    const float* __restrict__ pp, const float* __restrict__ td,
    const float* __restrict__ tf, float* __restrict__ out)
{
    size_t i4 = (size_t)blockIdx.x * 256 + threadIdx.x;
    size_t i = i4 * 4;
    int h = (int)(i & (HDIM - 1));

    union { uint2 u; __half hh[4]; } KU, VU, RU;
    KU.u = *(const uint2*)(g_kh + i);
    VU.u = *(const uint2*)(g_vh + i);
    RU.u = *(const uint2*)(g_rh + i);

    float4 p4 = *(const float4*)(pp + i);
    float4 a4 = *(const float4*)(aa + i);
    float4 b4 = *(const float4*)(bb + i);
    float4 tf4 = *(const float4*)(tf + h);
    float4 td4 = *(const float4*)(td + h);

    float4 na4, nb4, q24;
    float* p = &p4.x;  float* a = &a4.x;  float* b = &b4.x;
    float* tff = &tf4.x; float* tdd = &td4.x;
    float* na = &na4.x; float* nb = &nb4.x; float* q2 = &q24.x;

    union { __half hh[4]; uint2 u; } RW;

#pragma unroll
    for (int j = 0; j < 4; j++) {
        float kk = __half2float(KU.hh[j]);
        float vv = __half2float(VU.hh[j]);
        float rp = __half2float(RU.hh[j]);
        float ww = tff[j] + kk;
        float qq = fmaxf(p[j], ww);
        float e1 = expf(p[j] - qq);
        float e2 = expf(ww - qq);
        float wkv = (e1 * a[j] + e2 * vv) / (e1 * b[j] + e2);
        float w2 = p[j] + tdd[j];
        float qb = fmaxf(w2, kk);
        float e1b = expf(w2 - qb);
        float e2b = expf(kk - qb);
        na[j] = e1b * a[j] + e2b * vv;
        nb[j] = e1b * b[j] + e2b;
        q2[j] = qb;
        float r = 1.f / (1.f + expf(-rp));
        RW.hh[j] = __float2half_rn(r * wkv);
    }

    *(uint2*)(g_rw + tiled_off(i >> 10, h)) = RW.u;
    *(float4*)(out + 2 * NBH + i) = na4;  // slot 2: next_aa
    *(float4*)(out + 3 * NBH + i) = nb4;  // slot 3: next_bb
    *(float4*)(out + 4 * NBH + i) = q24;  // slot 4: qq2
}

// ---------------------------------------------------------------------------
extern "C" void kernel_launch(void* const* d_in, const int* in_sizes, int n_in,
                              void* d_out, int out_size)
{
    const float* x     = (const float*)d_in[0];
    const float* alpha = (const float*)d_in[1];
    const float* aa    = (const float*)d_in[2];
    const float* bb    = (const float*)d_in[3];
    const float* pp    = (const float*)d_in[4];
    const float* td    = (const float*)d_in[5];
    const float* tf    = (const float*)d_in[6];
    const float* mk    = (const float*)d_in[7];
    const float* mv    = (const float*)d_in[8];
    const float* mr    = (const float*)d_in[9];
    const float* Wk    = (const float*)d_in[10];
    const float* Wv    = (const float*)d_in[11];
    const float* Wr    = (const float*)d_in[12];
    const float* Wo    = (const float*)d_in[13];
    float* out = (float*)d_out;

    cudaFuncSetAttribute(gemm_mma<true>,  cudaFuncAttributeMaxDynamicSharedMemorySize, SMEM_TOT);
    cudaFuncSetAttribute(gemm_mma<false>, cudaFuncAttributeMaxDynamicSharedMemorySize, SMEM_TOT);

    prep_act<<<(unsigned)(NBH / 1024), 256>>>(x, alpha, mk, mv, mr, out);
    prep_w<<<dim3((unsigned)(NHH / 1024), 4), 256>>>(Wk, Wv, Wr, Wo);

    dim3 g3(HDIM / BN, BDIM / BM, 3);
    gemm_mma<true><<<g3, GT, SMEM_TOT>>>(0, nullptr);

    ew_kernel<<<(unsigned)(NBH / 1024), 256>>>(aa, bb, pp, td, tf, out);

    dim3 g1(HDIM / BN, BDIM / BM, 1);
    gemm_mma<false><<<g1, GT, SMEM_TOT>>>(3, out);
}